// round 14
// baseline (speedup 1.0000x reference)
#include <cuda_runtime.h>
#include <cuda_fp16.h>
#include <math.h>
#include <stdint.h>

// ---------------- problem constants ----------------
constexpr int LL   = 4608;
constexpr int HIDC = 3072;
constexpr int NHC  = 24;
constexpr int HDC  = 128;
constexpr int MLPC = 12288;
constexpr int RK   = 32;
constexpr int D3H  = 3 * HIDC;          // 9216
constexpr int NQKV = 3 * HIDC + MLPC;   // 21504
constexpr int NCAT = HIDC + MLPC;       // 15360
constexpr int KSPL = 8;                 // k-split for low-rank GEMM

// ---------------- scratch (device globals) ----------------
__device__ float  g_mod[D3H];
__device__ float  g_silu[HIDC];
__device__ __half g_xmodh[(size_t)LL * HIDC];
__device__ __half g_yh[(size_t)LL * NCAT];      // attn | gelu(mlp)  (GEMM2 A)
__device__ __half g_qh[(size_t)LL * HIDC];
__device__ __half g_kh[(size_t)LL * HIDC];
__device__ __half g_vh[(size_t)LL * HIDC];
__device__ __half g_t1h[LL * RK];
__device__ __half g_t2h[LL * RK];
__device__ float  g_tp[(size_t)KSPL * LL * RK]; // low-rank k-split partials
__device__ __half g_w1h[(size_t)NQKV * HIDC];
__device__ __half g_w2h[(size_t)HIDC * NCAT];
__device__ __half g_lu1h[NQKV * RK];
__device__ __half g_lu2h[HIDC * RK];
__device__ __half g_ld1h[RK * HIDC];
__device__ __half g_ld2h[RK * NCAT];
__device__ __half g_zeroh[8];                   // zero-initialized

// ---------------- asm helpers ----------------
__device__ __forceinline__ uint32_t smem_u32(const void* p) {
    uint32_t a;
    asm("{ .reg .u64 t; cvta.to.shared.u64 t, %1; cvt.u32.u64 %0, t; }" : "=r"(a) : "l"(p));
    return a;
}
__device__ __forceinline__ void cp16s(uint32_t s, const void* g) {
    asm volatile("cp.async.cg.shared.global [%0], [%1], 16;" :: "r"(s), "l"(g));
}
#define CP_COMMIT() asm volatile("cp.async.commit_group;")
#define CP_WAIT(N)  asm volatile("cp.async.wait_group %0;" :: "n"(N))

__device__ __forceinline__ void ldsm4(uint32_t* r, uint32_t a) {
    asm volatile("ldmatrix.sync.aligned.m8n8.x4.shared.b16 {%0,%1,%2,%3}, [%4];"
                 : "=r"(r[0]), "=r"(r[1]), "=r"(r[2]), "=r"(r[3]) : "r"(a));
}
__device__ __forceinline__ void ldsm4t(uint32_t* r, uint32_t a) {
    asm volatile("ldmatrix.sync.aligned.m8n8.x4.trans.shared.b16 {%0,%1,%2,%3}, [%4];"
                 : "=r"(r[0]), "=r"(r[1]), "=r"(r[2]), "=r"(r[3]) : "r"(a));
}
__device__ __forceinline__ void hmma(float* c, const uint32_t* a, const uint32_t* b) {
    asm volatile(
        "mma.sync.aligned.m16n8k16.row.col.f32.f16.f16.f32 "
        "{%0,%1,%2,%3}, {%4,%5,%6,%7}, {%8,%9}, {%0,%1,%2,%3};"
        : "+f"(c[0]), "+f"(c[1]), "+f"(c[2]), "+f"(c[3])
        : "r"(a[0]), "r"(a[1]), "r"(a[2]), "r"(a[3]), "r"(b[0]), "r"(b[1]));
}
__device__ __forceinline__ uint32_t packh2(float x, float y) {
    __half2 h = __floats2half2_rn(x, y);
    return *(uint32_t*)&h;
}
__device__ __forceinline__ float gelu_f(float v) {
    float u = 0.7978845608028654f * (v + 0.044715f * v * v * v);
    float t = 1.f - 2.f / (__expf(2.f * u) + 1.f);
    return 0.5f * v * (1.f + t);
}

// ---------------- K0: convert weights to fp16 ----------------
__global__ __launch_bounds__(256) void k_half(const float* __restrict__ src, int which) {
    __half* dst = which == 0 ? g_w1h : which == 1 ? g_w2h : which == 2 ? g_lu1h :
                  which == 3 ? g_lu2h : which == 4 ? g_ld1h : g_ld2h;
    size_t i = ((size_t)blockIdx.x * 256 + threadIdx.x) * 8;
    float4 v0 = *(const float4*)(src + i);
    float4 v1 = *(const float4*)(src + i + 4);
    __half2 h[4];
    h[0] = __floats2half2_rn(v0.x, v0.y);
    h[1] = __floats2half2_rn(v0.z, v0.w);
    h[2] = __floats2half2_rn(v1.x, v1.y);
    h[3] = __floats2half2_rn(v1.z, v1.w);
    *(uint4*)(dst + i) = *(uint4*)h;
}

// ---------------- K0b: silu(vec) precompute ----------------
__global__ __launch_bounds__(256) void k_silu(const float* __restrict__ vec) {
    int i = blockIdx.x * 256 + threadIdx.x;
    float s = vec[i];
    g_silu[i] = s / (1.f + __expf(-s));
}

// ---------------- K1: mod = silu(vec) @ mod_w^T + mod_b (float4) ----------------
__global__ __launch_bounds__(256) void k_mod(const float* __restrict__ mod_w,
                                             const float* __restrict__ mod_b) {
    int j = blockIdx.x * 8 + (threadIdx.x >> 5);
    int lane = threadIdx.x & 31;
    if (j >= D3H) return;
    const float* wr = mod_w + (size_t)j * HIDC;
    float acc = 0.f;
    #pragma unroll 4
    for (int k = lane * 4; k < HIDC; k += 128) {
        float4 sv = *(const float4*)(g_silu + k);
        float4 wv = *(const float4*)(wr + k);
        acc += sv.x * wv.x + sv.y * wv.y + sv.z * wv.z + sv.w * wv.w;
    }
    #pragma unroll
    for (int o = 16; o; o >>= 1) acc += __shfl_xor_sync(0xffffffffu, acc, o);
    if (lane == 0) g_mod[j] = acc + mod_b[j];
}

// ---------------- K2: LayerNorm + modulation -> g_xmodh (fp16) ----------------
__global__ __launch_bounds__(256) void k_ln(const float* __restrict__ x) {
    __shared__ float rs[8], rs2[8];
    int m = blockIdx.x;
    const float* row = x + (size_t)m * HIDC;
    float v[12];
    float s = 0.f, s2 = 0.f;
    #pragma unroll
    for (int i = 0; i < 12; i++) {
        v[i] = row[threadIdx.x + i * 256];
        s += v[i]; s2 += v[i] * v[i];
    }
    int lane = threadIdx.x & 31, w = threadIdx.x >> 5;
    #pragma unroll
    for (int o = 16; o; o >>= 1) {
        s  += __shfl_xor_sync(0xffffffffu, s, o);
        s2 += __shfl_xor_sync(0xffffffffu, s2, o);
    }
    if (!lane) { rs[w] = s; rs2[w] = s2; }
    __syncthreads();
    float S = 0.f, S2 = 0.f;
    #pragma unroll
    for (int i = 0; i < 8; i++) { S += rs[i]; S2 += rs2[i]; }
    float mu = S * (1.f / HIDC);
    float var = S2 * (1.f / HIDC) - mu * mu;
    float rstd = rsqrtf(var + 1e-6f);
    __half* orow = g_xmodh + (size_t)m * HIDC;
    #pragma unroll
    for (int i = 0; i < 12; i++) {
        int c = threadIdx.x + i * 256;
        float xn = (v[i] - mu) * rstd;
        orow[c] = __float2half_rn(xn * (1.f + g_mod[HIDC + c]) + g_mod[c]);
    }
}

// ---------------- K3: low-rank t = A @ ld^T via tensor cores, k-split ----------------
constexpr int LRP = 72;   // smem pitch (halves)

__global__ __launch_bounds__(256) void k_lr(int K, int sel) {
    __shared__ __half smlr[128 * LRP + 32 * LRP];
    uint32_t sb = smem_u32(smlr);
    const __half* A = sel ? g_yh : g_xmodh;
    const __half* L = sel ? g_ld2h : g_ld1h;
    int m0 = blockIdx.x * 128;
    int kl = K / KSPL;
    int k0 = blockIdx.y * kl;
    int tid = threadIdx.x, lane = tid & 31, wid = tid >> 5;
    uint32_t sA = sb, sL = sb + (uint32_t)(128 * LRP) * 2;

    float acc[4][4];
    #pragma unroll
    for (int i = 0; i < 4; i++)
        #pragma unroll
        for (int j = 0; j < 4; j++) acc[i][j] = 0.f;

    for (int kc = 0; kc < kl; kc += 64) {
        #pragma unroll
        for (int j = 0; j < 4; j++) {
            int c = tid + j * 256;
            int r = c >> 3, ch = c & 7;
            cp16s(sA + (uint32_t)(r * LRP + ch * 8) * 2,
                  A + (size_t)(m0 + r) * K + k0 + kc + ch * 8);
        }
        {
            int r = tid >> 3, ch = tid & 7;
            cp16s(sL + (uint32_t)(r * LRP + ch * 8) * 2,
                  L + (size_t)r * K + k0 + kc + ch * 8);
        }
        CP_COMMIT(); CP_WAIT(0);
        __syncthreads();
        #pragma unroll
        for (int ks = 0; ks < 4; ks++) {
            uint32_t af[4];
            int r = wid * 16 + (lane & 15);
            int kc16 = ks * 16 + (lane >> 4) * 8;
            ldsm4(af, sA + (uint32_t)(r * LRP + kc16) * 2);
            uint32_t bf[2][4];
            #pragma unroll
            for (int fn = 0; fn < 2; fn++) {
                int nr = fn * 16 + (lane & 7) + ((lane >> 4) & 1) * 8;
                int kcb = ks * 16 + ((lane >> 3) & 1) * 8;
                ldsm4(bf[fn], sL + (uint32_t)(nr * LRP + kcb) * 2);
            }
            hmma(acc[0], af, &bf[0][0]);
            hmma(acc[1], af, &bf[0][2]);
            hmma(acc[2], af, &bf[1][0]);
            hmma(acc[3], af, &bf[1][2]);
        }
        __syncthreads();
    }

    int g = lane >> 2, tg = lane & 3;
    float* tp = g_tp + (size_t)blockIdx.y * LL * RK;
    int r0 = m0 + wid * 16 + g;
    #pragma unroll
    for (int j = 0; j < 4; j++) {
        tp[(size_t)r0 * RK + j * 8 + 2 * tg]           = acc[j][0];
        tp[(size_t)r0 * RK + j * 8 + 2 * tg + 1]       = acc[j][1];
        tp[(size_t)(r0 + 8) * RK + j * 8 + 2 * tg]     = acc[j][2];
        tp[(size_t)(r0 + 8) * RK + j * 8 + 2 * tg + 1] = acc[j][3];
    }
}

__global__ __launch_bounds__(256) void k_lrsum(int sel) {
    __half* t = sel ? g_t2h : g_t1h;
    int i = blockIdx.x * 256 + threadIdx.x;
    float s = 0.f;
    #pragma unroll
    for (int p = 0; p < KSPL; p++) s += g_tp[(size_t)p * LL * RK + i];
    t[i] = __float2half_rn(s);
}

// ---------------- fp16 mma GEMM: 128x128 tile, k-tile 64, 3 stages, 1 sync/tile ----------------
constexpr int HST = 72;                 // halves per smem row (64 data + 8 pad)
constexpr int TILE_H = 128 * HST;       // 9216 halves
constexpr int STAGE_H = 2 * TILE_H;     // 18432
constexpr int STG = 3;
constexpr int GEMM_SMEM = STG * STAGE_H * 2;  // 110592 B

// EPI==1: A=g_xmodh, fused epilogue -> fp16 q/k/v/gelu(mlp)
// EPI==2: A=g_yh, out = x + gate*(acc+bias) fp32
template <int EPI, int GRP>
__global__ __launch_bounds__(256, 2) void k_gemm(const float* __restrict__ bias,
                                                 float* __restrict__ Cout,
                                                 int K, int N, int ldc,
                                                 const float* __restrict__ xres) {
    extern __shared__ __half smh[];
    uint32_t sb = smem_u32(smh);
    const __half* A  = (EPI == 1) ? g_xmodh : g_yh;
    const __half* TL = (EPI == 1) ? g_t1h : g_t2h;
    const __half* W  = (EPI == 1) ? g_w1h : g_w2h;
    const __half* LU = (EPI == 1) ? g_lu1h : g_lu2h;

    const int NNB = N / 128;
    int bid = blockIdx.x;
    int group = bid / (GRP * NNB);
    int within = bid - group * (GRP * NNB);
    int mb = group * GRP + (within % GRP);
    int nb = within / GRP;
    int m0 = mb << 7, n0 = nb << 7;

    int tid = threadIdx.x, lane = tid & 31, wid = tid >> 5;
    int wm = wid >> 1, wn = wid & 1;               // 4x2 warp grid, warptile 32x64

    const int KTm = K / 64;
    const int KT = KTm + 1;                        // + low-rank tile (zero padded to 64)

    float acc[2][8][4];
    #pragma unroll
    for (int i = 0; i < 2; i++)
        #pragma unroll
        for (int j = 0; j < 8; j++)
            #pragma unroll
            for (int q = 0; q < 4; q++) acc[i][j][q] = 0.f;

    auto issue = [&](int kt) {
        int s = kt % STG;
        uint32_t base = sb + (uint32_t)s * STAGE_H * 2;
        bool mn = kt < KTm;
        #pragma unroll
        for (int j = 0; j < 8; j++) {
            int c = tid + j * 256;                 // 0..2047
            int mat = c >> 10;                     // 0: A, 1: B
            int idx = c & 1023;
            int r = idx >> 3, ch = idx & 7;        // row 0..127, 16B chunk 0..7
            uint32_t dst = base + (uint32_t)(mat * TILE_H + r * HST + ch * 8) * 2;
            const __half* src;
            if (mn) {
                src = mat ? W + (size_t)(n0 + r) * K + kt * 64 + ch * 8
                          : A + (size_t)(m0 + r) * K + kt * 64 + ch * 8;
            } else {
                if (ch < 4)
                    src = mat ? LU + (size_t)(n0 + r) * RK + ch * 8
                              : TL + (size_t)(m0 + r) * RK + ch * 8;
                else
                    src = g_zeroh;
            }
            cp16s(dst, src);
        }
    };

    issue(0); CP_COMMIT();
    issue(1); CP_COMMIT();

    for (int kt = 0; kt < KT; kt++) {
        CP_WAIT(1);
        __syncthreads();
        if (kt + 2 < KT) issue(kt + 2);
        CP_COMMIT();
        uint32_t sA = sb + (uint32_t)(kt % STG) * STAGE_H * 2;
        uint32_t sB = sA + TILE_H * 2;
        #pragma unroll
        for (int ks = 0; ks < 4; ks++) {
            uint32_t af[2][4];
            #pragma unroll
            for (int fm = 0; fm < 2; fm++) {
                int r = wm * 32 + fm * 16 + (lane & 15);
                int kc = ks * 16 + (lane >> 4) * 8;
                ldsm4(af[fm], sA + (uint32_t)(r * HST + kc) * 2);
            }
            uint32_t bf[4][4];
            #pragma unroll
            for (int fp = 0; fp < 4; fp++) {
                int nr = wn * 64 + fp * 16 + (lane & 7) + ((lane >> 4) & 1) * 8;
                int kc = ks * 16 + ((lane >> 3) & 1) * 8;
                ldsm4(bf[fp], sB + (uint32_t)(nr * HST + kc) * 2);
            }
            #pragma unroll
            for (int fm = 0; fm < 2; fm++)
                #pragma unroll
                for (int fn = 0; fn < 8; fn++)
                    hmma(acc[fm][fn], af[fm], &bf[fn >> 1][(fn & 1) * 2]);
        }
    }

    int g = lane >> 2, tg = lane & 3;
    if (EPI == 1) {
        __half* dst;
        size_t stride;
        int cbias;
        bool is_mlp = false;
        if (n0 < HIDC)            { dst = g_qh; stride = HIDC; cbias = 0; }
        else if (n0 < 2 * HIDC)   { dst = g_kh; stride = HIDC; cbias = HIDC; }
        else if (n0 < D3H)        { dst = g_vh; stride = HIDC; cbias = 2 * HIDC; }
        else { dst = g_yh; stride = NCAT; cbias = D3H - HIDC; is_mlp = true; }
        #pragma unroll
        for (int fm = 0; fm < 2; fm++) {
            int r0 = m0 + wm * 32 + fm * 16 + g;
            int r1 = r0 + 8;
            #pragma unroll
            for (int fn = 0; fn < 8; fn++) {
                int cc = n0 + wn * 64 + fn * 8 + 2 * tg;
                float v0 = acc[fm][fn][0] + bias[cc];
                float v1 = acc[fm][fn][1] + bias[cc + 1];
                float v2 = acc[fm][fn][2] + bias[cc];
                float v3 = acc[fm][fn][3] + bias[cc + 1];
                if (is_mlp) {
                    v0 = gelu_f(v0); v1 = gelu_f(v1);
                    v2 = gelu_f(v2); v3 = gelu_f(v3);
                }
                int col = cc - cbias;
                *(__half2*)(dst + (size_t)r0 * stride + col) = __floats2half2_rn(v0, v1);
                *(__half2*)(dst + (size_t)r1 * stride + col) = __floats2half2_rn(v2, v3);
            }
        }
    } else {
        #pragma unroll
        for (int fm = 0; fm < 2; fm++) {
            int r0 = m0 + wm * 32 + fm * 16 + g;
            int r1 = r0 + 8;
            #pragma unroll
            for (int fn = 0; fn < 8; fn++) {
                int cc = n0 + wn * 64 + fn * 8 + 2 * tg;
                float v0 = acc[fm][fn][0] + bias[cc];
                float v1 = acc[fm][fn][1] + bias[cc + 1];
                float v2 = acc[fm][fn][2] + bias[cc];
                float v3 = acc[fm][fn][3] + bias[cc + 1];
                float gt0 = g_mod[2 * HIDC + cc], gt1 = g_mod[2 * HIDC + cc + 1];
                v0 = xres[(size_t)r0 * ldc + cc]     + gt0 * v0;
                v1 = xres[(size_t)r0 * ldc + cc + 1] + gt1 * v1;
                v2 = xres[(size_t)r1 * ldc + cc]     + gt0 * v2;
                v3 = xres[(size_t)r1 * ldc + cc + 1] + gt1 * v3;
                *(float2*)(Cout + (size_t)r0 * ldc + cc) = make_float2(v0, v1);
                *(float2*)(Cout + (size_t)r1 * ldc + cc) = make_float2(v2, v3);
            }
        }
    }
}

// ---------------- K5: RMSNorm(q,k) + RoPE, in-place fp16 ----------------
__global__ __launch_bounds__(128) void k_qknorm(const float* __restrict__ pe,
                                                const float* __restrict__ rqw,
                                                const float* __restrict__ rkw) {
    int l = blockIdx.x, h = blockIdx.y, d = threadIdx.x;
    size_t base = (size_t)l * HIDC + (size_t)h * 128;
    float qv = __half2float(g_qh[base + d]);
    float kv = __half2float(g_kh[base + d]);
    float q2 = qv * qv, k2 = kv * kv;
    #pragma unroll
    for (int o = 16; o; o >>= 1) {
        q2 += __shfl_xor_sync(0xffffffffu, q2, o);
        k2 += __shfl_xor_sync(0xffffffffu, k2, o);
    }
    __shared__ float sq[4], sk[4];
    int w = d >> 5, lane = d & 31;
    if (!lane) { sq[w] = q2; sk[w] = k2; }
    __syncthreads();
    float Q2 = sq[0] + sq[1] + sq[2] + sq[3];
    float K2 = sk[0] + sk[1] + sk[2] + sk[3];
    float qr = rsqrtf(Q2 * (1.f / HDC) + 1e-6f);
    float kr = rsqrtf(K2 * (1.f / HDC) + 1e-6f);
    float qn = qv * qr * rqw[d];
    float kn = kv * kr * rkw[d];
    int p = d >> 1, ii = d & 1;
    const float* rot = pe + (((size_t)l * 64 + p) * 2 + ii) * 2;
    float r0 = rot[0], r1 = rot[1];
    float qo = __shfl_xor_sync(0xffffffffu, qn, 1);
    float ko = __shfl_xor_sync(0xffffffffu, kn, 1);
    float qe = ii ? qo : qn, qod = ii ? qn : qo;
    float ke = ii ? ko : kn, kod = ii ? kn : ko;
    g_qh[base + d] = __float2half_rn(r0 * qe + r1 * qod);
    g_kh[base + d] = __float2half_rn(r0 * ke + r1 * kod);
}

// ---------------- K6: fp16 flash attention, 256q x 64k, 512 thr, shared K/V stream ----------------
constexpr int AST = 136;                        // halves per smem row
constexpr int OQ = 0;
constexpr int OS = 256 * AST;                   // stages base (after 256-row Q)
constexpr int STAGE_ATT = 128 * AST;            // per stage: K 64 rows + V 64 rows
constexpr int ATT_H = OS + 2 * STAGE_ATT;       // 69632 halves
constexpr int ATT_SMEM = ATT_H * 2;             // 139264 B

__global__ __launch_bounds__(512, 1) void k_attn() {
    extern __shared__ __half smh[];
    uint32_t sb = smem_u32(smh);

    int tid = threadIdx.x, lane = tid & 31, wid = tid >> 5;   // wid 0..15
    int g = lane >> 2, tg = lane & 3;
    int q0 = blockIdx.x * 256, h = blockIdx.y;
    size_t hb = (size_t)h * 128;
    const float sl2e = 0.08838834764831845f * 1.4426950408889634f;  // scale * log2(e)
    const int NKB = LL / 64;

    // load Q tile (256 rows, plain loads, once)
    for (int i = tid; i < 256 * 16; i += 512) {
        int r = i >> 4, c = (i & 15) * 8;
        *(uint4*)(smh + OQ + r * AST + c) =
            *(const uint4*)(g_qh + (size_t)(q0 + r) * HIDC + hb + c);
    }

    auto issueKV = [&](int kb) {
        uint32_t base = sb + (uint32_t)(OS + (kb & 1) * STAGE_ATT) * 2;
        int k0 = kb * 64;
        #pragma unroll
        for (int j = 0; j < 4; j++) {
            int c = tid + j * 512;                 // 0..2047
            int mat = c >> 10;                     // 0: K, 1: V
            int idx = c & 1023;
            int r = idx >> 4, ch = idx & 15;
            const __half* src = (mat ? g_vh : g_kh) + (size_t)(k0 + r) * HIDC + hb + ch * 8;
            uint32_t dst = base + (uint32_t)((mat * 64 + r) * AST + ch * 8) * 2;
            cp16s(dst, src);
        }
    };

    issueKV(0); CP_COMMIT();
    __syncthreads();

    float m0r = -1e30f, m1r = -1e30f, l0r = 0.f, l1r = 0.f;
    float oacc[16][4];
    #pragma unroll
    for (int i = 0; i < 16; i++)
        #pragma unroll
        for (int j = 0; j < 4; j++) oacc[i][j] = 0.f;

    for (int kb = 0; kb < NKB; kb++) {
        CP_WAIT(0);
        __syncthreads();
        if (kb + 1 < NKB) { issueKV(kb + 1); CP_COMMIT(); }
        uint32_t sK = sb + (uint32_t)(OS + (kb & 1) * STAGE_ATT) * 2;
        uint32_t sV = sK + (uint32_t)(64 * AST) * 2;

        // S = Q K^T  (Q frags from smem each ks)
        float sacc[8][4];
        #pragma unroll
        for (int i = 0; i < 8; i++)
            #pragma unroll
            for (int j = 0; j < 4; j++) sacc[i][j] = 0.f;
        #pragma unroll
        for (int ks = 0; ks < 8; ks++) {
            uint32_t qf[4];
            {
                int r = wid * 16 + (lane & 15);
                int kc = ks * 16 + (lane >> 4) * 8;
                ldsm4(qf, sb + (uint32_t)(OQ + r * AST + kc) * 2);
            }
            #pragma unroll
            for (int fp = 0; fp < 4; fp++) {
                uint32_t bf[4];
                int nr = fp * 16 + (lane & 7) + ((lane >> 4) & 1) * 8;
                int kc = ks * 16 + ((lane >> 3) & 1) * 8;
                ldsm4(bf, sK + (uint32_t)(nr * AST + kc) * 2);
                hmma(sacc[2 * fp], qf, &bf[0]);
                hmma(sacc[2 * fp + 1], qf, &bf[2]);
            }
        }

        // online softmax (base-2 domain)
        float mx0 = -1e30f, mx1 = -1e30f;
        #pragma unroll
        for (int fn = 0; fn < 8; fn++) {
            sacc[fn][0] *= sl2e; sacc[fn][1] *= sl2e;
            sacc[fn][2] *= sl2e; sacc[fn][3] *= sl2e;
            mx0 = fmaxf(mx0, fmaxf(sacc[fn][0], sacc[fn][1]));
            mx1 = fmaxf(mx1, fmaxf(sacc[fn][2], sacc[fn][3]));
        }
        mx0 = fmaxf(mx0, __shfl_xor_sync(0xffffffffu, mx0, 1));
        mx0 = fmaxf(mx0, __shfl_xor_sync(0xffffffffu, mx0, 2));
        mx1 = fmaxf(mx1, __shfl_xor_sync(0xffffffffu, mx1, 1));
        mx1 = fmaxf(mx1, __shfl_xor_sync(0xffffffffu, mx1, 2));
        float mn0 = fmaxf(m0r, mx0), mn1 = fmaxf(m1r, mx1);
        float cr0 = exp2f(m0r - mn0), cr1 = exp2f(m1r - mn1);
        float s0 = 0.f, s1 = 0.f;
        #pragma unroll
        for (int fn = 0; fn < 8; fn++) {
            sacc[fn][0] = exp2f(sacc[fn][0] - mn0);
            sacc[fn][1] = exp2f(sacc[fn][1] - mn0);
            sacc[fn][2] = exp2f(sacc[fn][2] - mn1);
            sacc[fn][3] = exp2f(sacc[fn][3] - mn1);
            s0 += sacc[fn][0] + sacc[fn][1];
            s1 += sacc[fn][2] + sacc[fn][3];
        }
        s0 += __shfl_xor_sync(0xffffffffu, s0, 1);
        s0 += __shfl_xor_sync(0xffffffffu, s0, 2);
        s1 += __shfl_xor_sync(0xffffffffu, s1, 1);
        s1 += __shfl_xor_sync(0xffffffffu, s1, 2);
        l0r = l0r * cr0 + s0;
        l1r = l1r * cr1 + s1;
        m0r = mn0; m1r = mn1;
        #pragma unroll
        for (int fn = 0; fn < 16; fn++) {
            oacc[fn][0] *= cr0; oacc[fn][1] *= cr0;
            oacc[fn][2] *= cr1; oacc[fn][3] *= cr1;
        }

        // O += P V
        #pragma unroll
        for (int ks = 0; ks < 4; ks++) {
            uint32_t pa[4];
            pa[0] = packh2(sacc[2 * ks][0],     sacc[2 * ks][1]);
            pa[1] = packh2(sacc[2 * ks][2],     sacc[2 * ks][3]);
            pa[2] = packh2(sacc[2 * ks + 1][0], sacc[2 * ks + 1][1]);
            pa[3] = packh2(sacc[2 * ks + 1][2], sacc[2 * ks + 1][3]);
            #pragma unroll
            for (int fp = 0; fp < 8; fp++) {
                uint32_t bf[4];
                int kr = ks * 16 + (lane & 7) + ((lane >> 3) & 1) * 8;
                int dc = fp * 16 + (lane >> 4) * 8;
                ldsm4t(bf, sV + (uint32_t)(kr * AST + dc) * 2);
                hmma(oacc[2 * fp], pa, &bf[0]);
                hmma(oacc[2 * fp + 1], pa, &bf[2]);
            }
        }
    }

    float inv0 = 1.f / l0r, inv1 = 1.f / l1r;
    int r0 = q0 + wid * 16 + g;
    #pragma unroll
    for (int fn = 0; fn < 16; fn++) {
        int c = (int)hb + fn * 8 + 2 * tg;
        *(__half2*)(g_yh + (size_t)r0 * NCAT + c) =
            __floats2half2_rn(oacc[fn][0] * inv0, oacc[fn][1] * inv0);
        *(__half2*)(g_yh + (size_t)(r0 + 8) * NCAT + c) =
            __floats2half2_rn(oacc[fn][2] * inv1, oacc[fn][3] * inv1);
    }
}

// ---------------- launch ----------------
extern "C" void kernel_launch(void* const* d_in, const int* in_sizes, int n_in,
                              void* d_out, int out_size) {
    const float* x     = (const float*)d_in[0];
    const float* vec   = (const float*)d_in[1];
    const float* pe    = (const float*)d_in[2];
    const float* mod_w = (const float*)d_in[3];
    const float* mod_b = (const float*)d_in[4];
    const float* w1    = (const float*)d_in[5];
    const float* b1    = (const float*)d_in[6];
    const float* ld1   = (const float*)d_in[7];
    const float* lu1   = (const float*)d_in[8];
    const float* w2    = (const float*)d_in[9];
    const float* b2    = (const float*)d_in[10];
    const float* ld2   = (const float*)d_in[11];
    const float* lu2   = (const float*)d_in[12];
    const float* rqw   = (const float*)d_in[13];
    const float* rkw   = (const float*)d_in[14];
    float* out = (float*)d_out;

    cudaFuncSetAttribute(k_attn, cudaFuncAttributeMaxDynamicSharedMemorySize, ATT_SMEM);
    cudaFuncSetAttribute((const void*)k_gemm<1, 36>, cudaFuncAttributeMaxDynamicSharedMemorySize, GEMM_SMEM);
    cudaFuncSetAttribute((const void*)k_gemm<2, 18>, cudaFuncAttributeMaxDynamicSharedMemorySize, GEMM_SMEM);

    k_silu<<<HIDC / 256, 256>>>(vec);
    k_mod<<<D3H / 8, 256>>>(mod_w, mod_b);
    k_half<<<RK * HIDC / 2048, 256>>>(ld1, 4);
    k_half<<<(int)((size_t)NQKV * HIDC / 2048), 256>>>(w1, 0);
    k_ln<<<LL, 256>>>(x);
    {
        dim3 glr(LL / 128, KSPL);
        k_lr<<<glr, 256>>>(HIDC, 0);
        k_lrsum<<<LL * RK / 256, 256>>>(0);
    }
    k_half<<<NQKV * RK / 2048, 256>>>(lu1, 2);
    {
        int nblocks = (LL / 128) * (NQKV / 128);   // 36 * 168
        k_gemm<1, 36><<<nblocks, 256, GEMM_SMEM>>>(b1, nullptr, HIDC, NQKV, NQKV, nullptr);
    }
    {
        dim3 gq(LL, NHC);
        k_qknorm<<<gq, 128>>>(pe, rqw, rkw);
    }
    {
        dim3 ga(LL / 256, NHC);   // (18, 24)
        k_attn<<<ga, 512, ATT_SMEM>>>();
    }
    k_half<<<RK * NCAT / 2048, 256>>>(ld2, 5);
    {
        dim3 glr(LL / 128, KSPL);
        k_lr<<<glr, 256>>>(NCAT, 1);
        k_lrsum<<<LL * RK / 256, 256>>>(1);
    }
    k_half<<<(int)((size_t)HIDC * NCAT / 2048), 256>>>(w2, 1);
    k_half<<<HIDC * RK / 2048, 256>>>(lu2, 3);
    {
        int nblocks = (LL / 128) * (HIDC / 128);   // 36 * 24
        k_gemm<2, 18><<<nblocks, 256, GEMM_SMEM>>>(b2, out, NCAT, HIDC, HIDC, x);
    }
}

// round 15
// speedup vs baseline: 1.0082x; 1.0082x over previous
#include <cuda_runtime.h>
#include <cuda_fp16.h>
#include <math.h>
#include <stdint.h>

// ---------------- problem constants ----------------
constexpr int LL   = 4608;
constexpr int HIDC = 3072;
constexpr int NHC  = 24;
constexpr int HDC  = 128;
constexpr int MLPC = 12288;
constexpr int RK   = 32;
constexpr int D3H  = 3 * HIDC;          // 9216
constexpr int NQKV = 3 * HIDC + MLPC;   // 21504
constexpr int NCAT = HIDC + MLPC;       // 15360
constexpr int KSPL = 8;                 // k-split for low-rank GEMM

// ---------------- scratch (device globals) ----------------
__device__ float  g_mod[D3H];
__device__ float  g_silu[HIDC];
__device__ __half g_xmodh[(size_t)LL * HIDC];
__device__ __half g_yh[(size_t)LL * NCAT];      // attn | gelu(mlp)  (GEMM2 A)
__device__ __half g_qh[(size_t)LL * HIDC];
__device__ __half g_kh[(size_t)LL * HIDC];
__device__ __half g_vh[(size_t)LL * HIDC];
__device__ __half g_t1h[LL * RK];
__device__ __half g_t2h[LL * RK];
__device__ float  g_tp[(size_t)KSPL * LL * RK]; // low-rank k-split partials
__device__ __half g_w1h[(size_t)NQKV * HIDC];
__device__ __half g_w2h[(size_t)HIDC * NCAT];
__device__ __half g_lu1h[NQKV * RK];
__device__ __half g_lu2h[HIDC * RK];
__device__ __half g_ld1h[RK * HIDC];
__device__ __half g_ld2h[RK * NCAT];
__device__ __half g_zeroh[8];                   // zero-initialized

// ---------------- asm helpers ----------------
__device__ __forceinline__ uint32_t smem_u32(const void* p) {
    uint32_t a;
    asm("{ .reg .u64 t; cvta.to.shared.u64 t, %1; cvt.u32.u64 %0, t; }" : "=r"(a) : "l"(p));
    return a;
}
__device__ __forceinline__ void cp16s(uint32_t s, const void* g) {
    asm volatile("cp.async.cg.shared.global [%0], [%1], 16;" :: "r"(s), "l"(g));
}
#define CP_COMMIT() asm volatile("cp.async.commit_group;")
#define CP_WAIT(N)  asm volatile("cp.async.wait_group %0;" :: "n"(N))

__device__ __forceinline__ void ldsm4(uint32_t* r, uint32_t a) {
    asm volatile("ldmatrix.sync.aligned.m8n8.x4.shared.b16 {%0,%1,%2,%3}, [%4];"
                 : "=r"(r[0]), "=r"(r[1]), "=r"(r[2]), "=r"(r[3]) : "r"(a));
}
__device__ __forceinline__ void ldsm4t(uint32_t* r, uint32_t a) {
    asm volatile("ldmatrix.sync.aligned.m8n8.x4.trans.shared.b16 {%0,%1,%2,%3}, [%4];"
                 : "=r"(r[0]), "=r"(r[1]), "=r"(r[2]), "=r"(r[3]) : "r"(a));
}
__device__ __forceinline__ void hmma(float* c, const uint32_t* a, const uint32_t* b) {
    asm volatile(
        "mma.sync.aligned.m16n8k16.row.col.f32.f16.f16.f32 "
        "{%0,%1,%2,%3}, {%4,%5,%6,%7}, {%8,%9}, {%0,%1,%2,%3};"
        : "+f"(c[0]), "+f"(c[1]), "+f"(c[2]), "+f"(c[3])
        : "r"(a[0]), "r"(a[1]), "r"(a[2]), "r"(a[3]), "r"(b[0]), "r"(b[1]));
}
__device__ __forceinline__ uint32_t packh2(float x, float y) {
    __half2 h = __floats2half2_rn(x, y);
    return *(uint32_t*)&h;
}
__device__ __forceinline__ float gelu_f(float v) {
    float u = 0.7978845608028654f * (v + 0.044715f * v * v * v);
    float t = 1.f - 2.f / (__expf(2.f * u) + 1.f);
    return 0.5f * v * (1.f + t);
}

// ---------------- K0: convert weights to fp16 ----------------
__global__ __launch_bounds__(256) void k_half(const float* __restrict__ src, int which) {
    __half* dst = which == 0 ? g_w1h : which == 1 ? g_w2h : which == 2 ? g_lu1h :
                  which == 3 ? g_lu2h : which == 4 ? g_ld1h : g_ld2h;
    size_t i = ((size_t)blockIdx.x * 256 + threadIdx.x) * 8;
    float4 v0 = *(const float4*)(src + i);
    float4 v1 = *(const float4*)(src + i + 4);
    __half2 h[4];
    h[0] = __floats2half2_rn(v0.x, v0.y);
    h[1] = __floats2half2_rn(v0.z, v0.w);
    h[2] = __floats2half2_rn(v1.x, v1.y);
    h[3] = __floats2half2_rn(v1.z, v1.w);
    *(uint4*)(dst + i) = *(uint4*)h;
}

// ---------------- K0b: silu(vec) precompute ----------------
__global__ __launch_bounds__(256) void k_silu(const float* __restrict__ vec) {
    int i = blockIdx.x * 256 + threadIdx.x;
    float s = vec[i];
    g_silu[i] = s / (1.f + __expf(-s));
}

// ---------------- K1: mod = silu(vec) @ mod_w^T + mod_b (float4) ----------------
__global__ __launch_bounds__(256) void k_mod(const float* __restrict__ mod_w,
                                             const float* __restrict__ mod_b) {
    int j = blockIdx.x * 8 + (threadIdx.x >> 5);
    int lane = threadIdx.x & 31;
    if (j >= D3H) return;
    const float* wr = mod_w + (size_t)j * HIDC;
    float acc = 0.f;
    #pragma unroll 4
    for (int k = lane * 4; k < HIDC; k += 128) {
        float4 sv = *(const float4*)(g_silu + k);
        float4 wv = *(const float4*)(wr + k);
        acc += sv.x * wv.x + sv.y * wv.y + sv.z * wv.z + sv.w * wv.w;
    }
    #pragma unroll
    for (int o = 16; o; o >>= 1) acc += __shfl_xor_sync(0xffffffffu, acc, o);
    if (lane == 0) g_mod[j] = acc + mod_b[j];
}

// ---------------- K2: LayerNorm + modulation -> g_xmodh (fp16) ----------------
__global__ __launch_bounds__(256) void k_ln(const float* __restrict__ x) {
    __shared__ float rs[8], rs2[8];
    int m = blockIdx.x;
    const float* row = x + (size_t)m * HIDC;
    float v[12];
    float s = 0.f, s2 = 0.f;
    #pragma unroll
    for (int i = 0; i < 12; i++) {
        v[i] = row[threadIdx.x + i * 256];
        s += v[i]; s2 += v[i] * v[i];
    }
    int lane = threadIdx.x & 31, w = threadIdx.x >> 5;
    #pragma unroll
    for (int o = 16; o; o >>= 1) {
        s  += __shfl_xor_sync(0xffffffffu, s, o);
        s2 += __shfl_xor_sync(0xffffffffu, s2, o);
    }
    if (!lane) { rs[w] = s; rs2[w] = s2; }
    __syncthreads();
    float S = 0.f, S2 = 0.f;
    #pragma unroll
    for (int i = 0; i < 8; i++) { S += rs[i]; S2 += rs2[i]; }
    float mu = S * (1.f / HIDC);
    float var = S2 * (1.f / HIDC) - mu * mu;
    float rstd = rsqrtf(var + 1e-6f);
    __half* orow = g_xmodh + (size_t)m * HIDC;
    #pragma unroll
    for (int i = 0; i < 12; i++) {
        int c = threadIdx.x + i * 256;
        float xn = (v[i] - mu) * rstd;
        orow[c] = __float2half_rn(xn * (1.f + g_mod[HIDC + c]) + g_mod[c]);
    }
}

// ---------------- K3: low-rank t = A @ ld^T via tensor cores, k-split ----------------
constexpr int LRP = 72;   // smem pitch (halves)

__global__ __launch_bounds__(256) void k_lr(int K, int sel) {
    __shared__ __half smlr[128 * LRP + 32 * LRP];
    uint32_t sb = smem_u32(smlr);
    const __half* A = sel ? g_yh : g_xmodh;
    const __half* L = sel ? g_ld2h : g_ld1h;
    int m0 = blockIdx.x * 128;
    int kl = K / KSPL;
    int k0 = blockIdx.y * kl;
    int tid = threadIdx.x, lane = tid & 31, wid = tid >> 5;
    uint32_t sA = sb, sL = sb + (uint32_t)(128 * LRP) * 2;

    float acc[4][4];
    #pragma unroll
    for (int i = 0; i < 4; i++)
        #pragma unroll
        for (int j = 0; j < 4; j++) acc[i][j] = 0.f;

    for (int kc = 0; kc < kl; kc += 64) {
        #pragma unroll
        for (int j = 0; j < 4; j++) {
            int c = tid + j * 256;
            int r = c >> 3, ch = c & 7;
            cp16s(sA + (uint32_t)(r * LRP + ch * 8) * 2,
                  A + (size_t)(m0 + r) * K + k0 + kc + ch * 8);
        }
        {
            int r = tid >> 3, ch = tid & 7;
            cp16s(sL + (uint32_t)(r * LRP + ch * 8) * 2,
                  L + (size_t)r * K + k0 + kc + ch * 8);
        }
        CP_COMMIT(); CP_WAIT(0);
        __syncthreads();
        #pragma unroll
        for (int ks = 0; ks < 4; ks++) {
            uint32_t af[4];
            int r = wid * 16 + (lane & 15);
            int kc16 = ks * 16 + (lane >> 4) * 8;
            ldsm4(af, sA + (uint32_t)(r * LRP + kc16) * 2);
            uint32_t bf[2][4];
            #pragma unroll
            for (int fn = 0; fn < 2; fn++) {
                int nr = fn * 16 + (lane & 7) + ((lane >> 4) & 1) * 8;
                int kcb = ks * 16 + ((lane >> 3) & 1) * 8;
                ldsm4(bf[fn], sL + (uint32_t)(nr * LRP + kcb) * 2);
            }
            hmma(acc[0], af, &bf[0][0]);
            hmma(acc[1], af, &bf[0][2]);
            hmma(acc[2], af, &bf[1][0]);
            hmma(acc[3], af, &bf[1][2]);
        }
        __syncthreads();
    }

    int g = lane >> 2, tg = lane & 3;
    float* tp = g_tp + (size_t)blockIdx.y * LL * RK;
    int r0 = m0 + wid * 16 + g;
    #pragma unroll
    for (int j = 0; j < 4; j++) {
        tp[(size_t)r0 * RK + j * 8 + 2 * tg]           = acc[j][0];
        tp[(size_t)r0 * RK + j * 8 + 2 * tg + 1]       = acc[j][1];
        tp[(size_t)(r0 + 8) * RK + j * 8 + 2 * tg]     = acc[j][2];
        tp[(size_t)(r0 + 8) * RK + j * 8 + 2 * tg + 1] = acc[j][3];
    }
}

__global__ __launch_bounds__(256) void k_lrsum(int sel) {
    __half* t = sel ? g_t2h : g_t1h;
    int i = blockIdx.x * 256 + threadIdx.x;
    float s = 0.f;
    #pragma unroll
    for (int p = 0; p < KSPL; p++) s += g_tp[(size_t)p * LL * RK + i];
    t[i] = __float2half_rn(s);
}

// ---------------- fp16 mma GEMM: 128x128 tile, k-tile 64, 3 stages, 1 sync/tile ----------------
constexpr int HST = 72;                 // halves per smem row (64 data + 8 pad)
constexpr int TILE_H = 128 * HST;       // 9216 halves
constexpr int STAGE_H = 2 * TILE_H;     // 18432
constexpr int STG = 3;
constexpr int GEMM_SMEM = STG * STAGE_H * 2;  // 110592 B

// EPI==1: A=g_xmodh, fused epilogue -> fp16 q/k/v/gelu(mlp)
// EPI==2: A=g_yh, out = x + gate*(acc+bias) fp32
template <int EPI, int GRP>
__global__ __launch_bounds__(256, 2) void k_gemm(const float* __restrict__ bias,
                                                 float* __restrict__ Cout,
                                                 int K, int N, int ldc,
                                                 const float* __restrict__ xres) {
    extern __shared__ __half smh[];
    uint32_t sb = smem_u32(smh);
    const __half* A  = (EPI == 1) ? g_xmodh : g_yh;
    const __half* TL = (EPI == 1) ? g_t1h : g_t2h;
    const __half* W  = (EPI == 1) ? g_w1h : g_w2h;
    const __half* LU = (EPI == 1) ? g_lu1h : g_lu2h;

    const int NNB = N / 128;
    int bid = blockIdx.x;
    int group = bid / (GRP * NNB);
    int within = bid - group * (GRP * NNB);
    int mb = group * GRP + (within % GRP);
    int nb = within / GRP;
    int m0 = mb << 7, n0 = nb << 7;

    int tid = threadIdx.x, lane = tid & 31, wid = tid >> 5;
    int wm = wid >> 1, wn = wid & 1;               // 4x2 warp grid, warptile 32x64

    const int KTm = K / 64;
    const int KT = KTm + 1;                        // + low-rank tile (zero padded to 64)

    float acc[2][8][4];
    #pragma unroll
    for (int i = 0; i < 2; i++)
        #pragma unroll
        for (int j = 0; j < 8; j++)
            #pragma unroll
            for (int q = 0; q < 4; q++) acc[i][j][q] = 0.f;

    auto issue = [&](int kt) {
        int s = kt % STG;
        uint32_t base = sb + (uint32_t)s * STAGE_H * 2;
        bool mn = kt < KTm;
        #pragma unroll
        for (int j = 0; j < 8; j++) {
            int c = tid + j * 256;                 // 0..2047
            int mat = c >> 10;                     // 0: A, 1: B
            int idx = c & 1023;
            int r = idx >> 3, ch = idx & 7;        // row 0..127, 16B chunk 0..7
            uint32_t dst = base + (uint32_t)(mat * TILE_H + r * HST + ch * 8) * 2;
            const __half* src;
            if (mn) {
                src = mat ? W + (size_t)(n0 + r) * K + kt * 64 + ch * 8
                          : A + (size_t)(m0 + r) * K + kt * 64 + ch * 8;
            } else {
                if (ch < 4)
                    src = mat ? LU + (size_t)(n0 + r) * RK + ch * 8
                              : TL + (size_t)(m0 + r) * RK + ch * 8;
                else
                    src = g_zeroh;
            }
            cp16s(dst, src);
        }
    };

    issue(0); CP_COMMIT();
    issue(1); CP_COMMIT();

    for (int kt = 0; kt < KT; kt++) {
        CP_WAIT(1);
        __syncthreads();
        if (kt + 2 < KT) issue(kt + 2);
        CP_COMMIT();
        uint32_t sA = sb + (uint32_t)(kt % STG) * STAGE_H * 2;
        uint32_t sB = sA + TILE_H * 2;
        #pragma unroll
        for (int ks = 0; ks < 4; ks++) {
            uint32_t af[2][4];
            #pragma unroll
            for (int fm = 0; fm < 2; fm++) {
                int r = wm * 32 + fm * 16 + (lane & 15);
                int kc = ks * 16 + (lane >> 4) * 8;
                ldsm4(af[fm], sA + (uint32_t)(r * HST + kc) * 2);
            }
            uint32_t bf[4][4];
            #pragma unroll
            for (int fp = 0; fp < 4; fp++) {
                int nr = wn * 64 + fp * 16 + (lane & 7) + ((lane >> 4) & 1) * 8;
                int kc = ks * 16 + ((lane >> 3) & 1) * 8;
                ldsm4(bf[fp], sB + (uint32_t)(nr * HST + kc) * 2);
            }
            #pragma unroll
            for (int fm = 0; fm < 2; fm++)
                #pragma unroll
                for (int fn = 0; fn < 8; fn++)
                    hmma(acc[fm][fn], af[fm], &bf[fn >> 1][(fn & 1) * 2]);
        }
    }

    int g = lane >> 2, tg = lane & 3;
    if (EPI == 1) {
        __half* dst;
        size_t stride;
        int cbias;
        bool is_mlp = false;
        if (n0 < HIDC)            { dst = g_qh; stride = HIDC; cbias = 0; }
        else if (n0 < 2 * HIDC)   { dst = g_kh; stride = HIDC; cbias = HIDC; }
        else if (n0 < D3H)        { dst = g_vh; stride = HIDC; cbias = 2 * HIDC; }
        else { dst = g_yh; stride = NCAT; cbias = D3H - HIDC; is_mlp = true; }
        #pragma unroll
        for (int fm = 0; fm < 2; fm++) {
            int r0 = m0 + wm * 32 + fm * 16 + g;
            int r1 = r0 + 8;
            #pragma unroll
            for (int fn = 0; fn < 8; fn++) {
                int cc = n0 + wn * 64 + fn * 8 + 2 * tg;
                float v0 = acc[fm][fn][0] + bias[cc];
                float v1 = acc[fm][fn][1] + bias[cc + 1];
                float v2 = acc[fm][fn][2] + bias[cc];
                float v3 = acc[fm][fn][3] + bias[cc + 1];
                if (is_mlp) {
                    v0 = gelu_f(v0); v1 = gelu_f(v1);
                    v2 = gelu_f(v2); v3 = gelu_f(v3);
                }
                int col = cc - cbias;
                *(__half2*)(dst + (size_t)r0 * stride + col) = __floats2half2_rn(v0, v1);
                *(__half2*)(dst + (size_t)r1 * stride + col) = __floats2half2_rn(v2, v3);
            }
        }
    } else {
        #pragma unroll
        for (int fm = 0; fm < 2; fm++) {
            int r0 = m0 + wm * 32 + fm * 16 + g;
            int r1 = r0 + 8;
            #pragma unroll
            for (int fn = 0; fn < 8; fn++) {
                int cc = n0 + wn * 64 + fn * 8 + 2 * tg;
                float v0 = acc[fm][fn][0] + bias[cc];
                float v1 = acc[fm][fn][1] + bias[cc + 1];
                float v2 = acc[fm][fn][2] + bias[cc];
                float v3 = acc[fm][fn][3] + bias[cc + 1];
                float gt0 = g_mod[2 * HIDC + cc], gt1 = g_mod[2 * HIDC + cc + 1];
                v0 = xres[(size_t)r0 * ldc + cc]     + gt0 * v0;
                v1 = xres[(size_t)r0 * ldc + cc + 1] + gt1 * v1;
                v2 = xres[(size_t)r1 * ldc + cc]     + gt0 * v2;
                v3 = xres[(size_t)r1 * ldc + cc + 1] + gt1 * v3;
                *(float2*)(Cout + (size_t)r0 * ldc + cc) = make_float2(v0, v1);
                *(float2*)(Cout + (size_t)r1 * ldc + cc) = make_float2(v2, v3);
            }
        }
    }
}

// ---------------- K5: RMSNorm(q,k) + RoPE, in-place fp16 ----------------
__global__ __launch_bounds__(128) void k_qknorm(const float* __restrict__ pe,
                                                const float* __restrict__ rqw,
                                                const float* __restrict__ rkw) {
    int l = blockIdx.x, h = blockIdx.y, d = threadIdx.x;
    size_t base = (size_t)l * HIDC + (size_t)h * 128;
    float qv = __half2float(g_qh[base + d]);
    float kv = __half2float(g_kh[base + d]);
    float q2 = qv * qv, k2 = kv * kv;
    #pragma unroll
    for (int o = 16; o; o >>= 1) {
        q2 += __shfl_xor_sync(0xffffffffu, q2, o);
        k2 += __shfl_xor_sync(0xffffffffu, k2, o);
    }
    __shared__ float sq[4], sk[4];
    int w = d >> 5, lane = d & 31;
    if (!lane) { sq[w] = q2; sk[w] = k2; }
    __syncthreads();
    float Q2 = sq[0] + sq[1] + sq[2] + sq[3];
    float K2 = sk[0] + sk[1] + sk[2] + sk[3];
    float qr = rsqrtf(Q2 * (1.f / HDC) + 1e-6f);
    float kr = rsqrtf(K2 * (1.f / HDC) + 1e-6f);
    float qn = qv * qr * rqw[d];
    float kn = kv * kr * rkw[d];
    int p = d >> 1, ii = d & 1;
    const float* rot = pe + (((size_t)l * 64 + p) * 2 + ii) * 2;
    float r0 = rot[0], r1 = rot[1];
    float qo = __shfl_xor_sync(0xffffffffu, qn, 1);
    float ko = __shfl_xor_sync(0xffffffffu, kn, 1);
    float qe = ii ? qo : qn, qod = ii ? qn : qo;
    float ke = ii ? ko : kn, kod = ii ? kn : ko;
    g_qh[base + d] = __float2half_rn(r0 * qe + r1 * qod);
    g_kh[base + d] = __float2half_rn(r0 * ke + r1 * kod);
}

// ---------------- K6: fp16 flash attention, 256q x 64k, 512 thr, shared K/V stream ----------------
constexpr int AST = 136;                        // halves per smem row
constexpr int OQ = 0;
constexpr int OS = 256 * AST;                   // stages base (after 256-row Q)
constexpr int STAGE_ATT = 128 * AST;            // per stage: K 64 rows + V 64 rows
constexpr int ATT_H = OS + 2 * STAGE_ATT;       // 69632 halves
constexpr int ATT_SMEM = ATT_H * 2;             // 139264 B

__global__ __launch_bounds__(512, 1) void k_attn() {
    extern __shared__ __half smh[];
    uint32_t sb = smem_u32(smh);

    int tid = threadIdx.x, lane = tid & 31, wid = tid >> 5;   // wid 0..15
    int g = lane >> 2, tg = lane & 3;
    int q0 = blockIdx.x * 256, h = blockIdx.y;
    size_t hb = (size_t)h * 128;
    const float sl2e = 0.08838834764831845f * 1.4426950408889634f;  // scale * log2(e)
    const int NKB = LL / 64;

    // load Q tile (256 rows, plain loads, once)
    for (int i = tid; i < 256 * 16; i += 512) {
        int r = i >> 4, c = (i & 15) * 8;
        *(uint4*)(smh + OQ + r * AST + c) =
            *(const uint4*)(g_qh + (size_t)(q0 + r) * HIDC + hb + c);
    }

    auto issueKV = [&](int kb) {
        uint32_t base = sb + (uint32_t)(OS + (kb & 1) * STAGE_ATT) * 2;
        int k0 = kb * 64;
        #pragma unroll
        for (int j = 0; j < 4; j++) {
            int c = tid + j * 512;                 // 0..2047
            int mat = c >> 10;                     // 0: K, 1: V
            int idx = c & 1023;
            int r = idx >> 4, ch = idx & 15;
            const __half* src = (mat ? g_vh : g_kh) + (size_t)(k0 + r) * HIDC + hb + ch * 8;
            uint32_t dst = base + (uint32_t)((mat * 64 + r) * AST + ch * 8) * 2;
            cp16s(dst, src);
        }
    };

    issueKV(0); CP_COMMIT();
    __syncthreads();

    float m0r = -1e30f, m1r = -1e30f, l0r = 0.f, l1r = 0.f;
    float oacc[16][4];
    #pragma unroll
    for (int i = 0; i < 16; i++)
        #pragma unroll
        for (int j = 0; j < 4; j++) oacc[i][j] = 0.f;

    for (int kb = 0; kb < NKB; kb++) {
        CP_WAIT(0);
        __syncthreads();
        if (kb + 1 < NKB) { issueKV(kb + 1); CP_COMMIT(); }
        uint32_t sK = sb + (uint32_t)(OS + (kb & 1) * STAGE_ATT) * 2;
        uint32_t sV = sK + (uint32_t)(64 * AST) * 2;

        // S = Q K^T  (Q frags from smem each ks)
        float sacc[8][4];
        #pragma unroll
        for (int i = 0; i < 8; i++)
            #pragma unroll
            for (int j = 0; j < 4; j++) sacc[i][j] = 0.f;
        #pragma unroll
        for (int ks = 0; ks < 8; ks++) {
            uint32_t qf[4];
            {
                int r = wid * 16 + (lane & 15);
                int kc = ks * 16 + (lane >> 4) * 8;
                ldsm4(qf, sb + (uint32_t)(OQ + r * AST + kc) * 2);
            }
            #pragma unroll
            for (int fp = 0; fp < 4; fp++) {
                uint32_t bf[4];
                int nr = fp * 16 + (lane & 7) + ((lane >> 4) & 1) * 8;
                int kc = ks * 16 + ((lane >> 3) & 1) * 8;
                ldsm4(bf, sK + (uint32_t)(nr * AST + kc) * 2);
                hmma(sacc[2 * fp], qf, &bf[0]);
                hmma(sacc[2 * fp + 1], qf, &bf[2]);
            }
        }

        // online softmax (base-2 domain)
        float mx0 = -1e30f, mx1 = -1e30f;
        #pragma unroll
        for (int fn = 0; fn < 8; fn++) {
            sacc[fn][0] *= sl2e; sacc[fn][1] *= sl2e;
            sacc[fn][2] *= sl2e; sacc[fn][3] *= sl2e;
            mx0 = fmaxf(mx0, fmaxf(sacc[fn][0], sacc[fn][1]));
            mx1 = fmaxf(mx1, fmaxf(sacc[fn][2], sacc[fn][3]));
        }
        mx0 = fmaxf(mx0, __shfl_xor_sync(0xffffffffu, mx0, 1));
        mx0 = fmaxf(mx0, __shfl_xor_sync(0xffffffffu, mx0, 2));
        mx1 = fmaxf(mx1, __shfl_xor_sync(0xffffffffu, mx1, 1));
        mx1 = fmaxf(mx1, __shfl_xor_sync(0xffffffffu, mx1, 2));
        float mn0 = fmaxf(m0r, mx0), mn1 = fmaxf(m1r, mx1);
        float cr0 = exp2f(m0r - mn0), cr1 = exp2f(m1r - mn1);
        float s0 = 0.f, s1 = 0.f;
        #pragma unroll
        for (int fn = 0; fn < 8; fn++) {
            sacc[fn][0] = exp2f(sacc[fn][0] - mn0);
            sacc[fn][1] = exp2f(sacc[fn][1] - mn0);
            sacc[fn][2] = exp2f(sacc[fn][2] - mn1);
            sacc[fn][3] = exp2f(sacc[fn][3] - mn1);
            s0 += sacc[fn][0] + sacc[fn][1];
            s1 += sacc[fn][2] + sacc[fn][3];
        }
        s0 += __shfl_xor_sync(0xffffffffu, s0, 1);
        s0 += __shfl_xor_sync(0xffffffffu, s0, 2);
        s1 += __shfl_xor_sync(0xffffffffu, s1, 1);
        s1 += __shfl_xor_sync(0xffffffffu, s1, 2);
        l0r = l0r * cr0 + s0;
        l1r = l1r * cr1 + s1;
        m0r = mn0; m1r = mn1;
        #pragma unroll
        for (int fn = 0; fn < 16; fn++) {
            oacc[fn][0] *= cr0; oacc[fn][1] *= cr0;
            oacc[fn][2] *= cr1; oacc[fn][3] *= cr1;
        }

        // O += P V
        #pragma unroll
        for (int ks = 0; ks < 4; ks++) {
            uint32_t pa[4];
            pa[0] = packh2(sacc[2 * ks][0],     sacc[2 * ks][1]);
            pa[1] = packh2(sacc[2 * ks][2],     sacc[2 * ks][3]);
            pa[2] = packh2(sacc[2 * ks + 1][0], sacc[2 * ks + 1][1]);
            pa[3] = packh2(sacc[2 * ks + 1][2], sacc[2 * ks + 1][3]);
            #pragma unroll
            for (int fp = 0; fp < 8; fp++) {
                uint32_t bf[4];
                int kr = ks * 16 + (lane & 7) + ((lane >> 3) & 1) * 8;
                int dc = fp * 16 + (lane >> 4) * 8;
                ldsm4t(bf, sV + (uint32_t)(kr * AST + dc) * 2);
                hmma(oacc[2 * fp], pa, &bf[0]);
                hmma(oacc[2 * fp + 1], pa, &bf[2]);
            }
        }
    }

    float inv0 = 1.f / l0r, inv1 = 1.f / l1r;
    int r0 = q0 + wid * 16 + g;
    #pragma unroll
    for (int fn = 0; fn < 16; fn++) {
        int c = (int)hb + fn * 8 + 2 * tg;
        *(__half2*)(g_yh + (size_t)r0 * NCAT + c) =
            __floats2half2_rn(oacc[fn][0] * inv0, oacc[fn][1] * inv0);
        *(__half2*)(g_yh + (size_t)(r0 + 8) * NCAT + c) =
            __floats2half2_rn(oacc[fn][2] * inv1, oacc[fn][3] * inv1);
    }
}

// ---------------- launch ----------------
extern "C" void kernel_launch(void* const* d_in, const int* in_sizes, int n_in,
                              void* d_out, int out_size) {
    const float* x     = (const float*)d_in[0];
    const float* vec   = (const float*)d_in[1];
    const float* pe    = (const float*)d_in[2];
    const float* mod_w = (const float*)d_in[3];
    const float* mod_b = (const float*)d_in[4];
    const float* w1    = (const float*)d_in[5];
    const float* b1    = (const float*)d_in[6];
    const float* ld1   = (const float*)d_in[7];
    const float* lu1   = (const float*)d_in[8];
    const float* w2    = (const float*)d_in[9];
    const float* b2    = (const float*)d_in[10];
    const float* ld2   = (const float*)d_in[11];
    const float* lu2   = (const float*)d_in[12];
    const float* rqw   = (const float*)d_in[13];
    const float* rkw   = (const float*)d_in[14];
    float* out = (float*)d_out;

    cudaFuncSetAttribute(k_attn, cudaFuncAttributeMaxDynamicSharedMemorySize, ATT_SMEM);
    cudaFuncSetAttribute((const void*)k_gemm<1, 36>, cudaFuncAttributeMaxDynamicSharedMemorySize, GEMM_SMEM);
    cudaFuncSetAttribute((const void*)k_gemm<2, 18>, cudaFuncAttributeMaxDynamicSharedMemorySize, GEMM_SMEM);

    k_silu<<<HIDC / 256, 256>>>(vec);
    k_mod<<<D3H / 8, 256>>>(mod_w, mod_b);
    k_half<<<RK * HIDC / 2048, 256>>>(ld1, 4);
    k_half<<<(int)((size_t)NQKV * HIDC / 2048), 256>>>(w1, 0);
    k_ln<<<LL, 256>>>(x);
    {
        dim3 glr(LL / 128, KSPL);
        k_lr<<<glr, 256>>>(HIDC, 0);
        k_lrsum<<<LL * RK / 256, 256>>>(0);
    }
    k_half<<<NQKV * RK / 2048, 256>>>(lu1, 2);
    {
        int nblocks = (LL / 128) * (NQKV / 128);   // 36 * 168
        k_gemm<1, 36><<<nblocks, 256, GEMM_SMEM>>>(b1, nullptr, HIDC, NQKV, NQKV, nullptr);
    }
    {
        dim3 gq(LL, NHC);
        k_qknorm<<<gq, 128>>>(pe, rqw, rkw);
    }
    {
        dim3 ga(LL / 256, NHC);   // (18, 24)
        k_attn<<<ga, 512, ATT_SMEM>>>();
    }
    k_half<<<RK * NCAT / 2048, 256>>>(ld2, 5);
    {
        dim3 glr(LL / 128, KSPL);
        k_lr<<<glr, 256>>>(NCAT, 1);
        k_lrsum<<<LL * RK / 256, 256>>>(1);
    }
    k_half<<<(int)((size_t)HIDC * NCAT / 2048), 256>>>(w2, 1);
    k_half<<<HIDC * RK / 2048, 256>>>(lu2, 3);
    {
        int nblocks = (LL / 128) * (HIDC / 128);   // 36 * 24
        k_gemm<2, 18><<<nblocks, 256, GEMM_SMEM>>>(b2, out, NCAT, HIDC, HIDC, x);
    }
}

// round 16
// speedup vs baseline: 1.0153x; 1.0070x over previous
#include <cuda_runtime.h>
#include <cuda_fp16.h>
#include <math.h>
#include <stdint.h>

// ---------------- problem constants ----------------
constexpr int LL   = 4608;
constexpr int HIDC = 3072;
constexpr int NHC  = 24;
constexpr int HDC  = 128;
constexpr int MLPC = 12288;
constexpr int RK   = 32;
constexpr int D3H  = 3 * HIDC;          // 9216
constexpr int NQKV = 3 * HIDC + MLPC;   // 21504
constexpr int NCAT = HIDC + MLPC;       // 15360
constexpr int KSPL = 8;                 // k-split for low-rank GEMM

// ---------------- scratch (device globals) ----------------
__device__ float  g_mod[D3H];
__device__ float  g_silu[HIDC];
__device__ __half g_xmodh[(size_t)LL * HIDC];
__device__ __half g_yh[(size_t)LL * NCAT];      // attn | gelu(mlp)  (GEMM2 A)
__device__ __half g_qh[(size_t)LL * HIDC];
__device__ __half g_kh[(size_t)LL * HIDC];
__device__ __half g_vh[(size_t)LL * HIDC];
__device__ __half g_t1h[LL * RK];
__device__ __half g_t2h[LL * RK];
__device__ float  g_tp[(size_t)KSPL * LL * RK]; // low-rank k-split partials
__device__ __half g_w1h[(size_t)NQKV * HIDC];
__device__ __half g_w2h[(size_t)HIDC * NCAT];
__device__ __half g_lu1h[NQKV * RK];
__device__ __half g_lu2h[HIDC * RK];
__device__ __half g_ld1h[RK * HIDC];
__device__ __half g_ld2h[RK * NCAT];
__device__ __half g_zeroh[8];                   // zero-initialized

// ---------------- asm helpers ----------------
__device__ __forceinline__ uint32_t smem_u32(const void* p) {
    uint32_t a;
    asm("{ .reg .u64 t; cvta.to.shared.u64 t, %1; cvt.u32.u64 %0, t; }" : "=r"(a) : "l"(p));
    return a;
}
__device__ __forceinline__ void cp16s(uint32_t s, const void* g) {
    asm volatile("cp.async.cg.shared.global [%0], [%1], 16;" :: "r"(s), "l"(g));
}
#define CP_COMMIT() asm volatile("cp.async.commit_group;")
#define CP_WAIT(N)  asm volatile("cp.async.wait_group %0;" :: "n"(N))

__device__ __forceinline__ void ldsm4(uint32_t* r, uint32_t a) {
    asm volatile("ldmatrix.sync.aligned.m8n8.x4.shared.b16 {%0,%1,%2,%3}, [%4];"
                 : "=r"(r[0]), "=r"(r[1]), "=r"(r[2]), "=r"(r[3]) : "r"(a));
}
__device__ __forceinline__ void ldsm4t(uint32_t* r, uint32_t a) {
    asm volatile("ldmatrix.sync.aligned.m8n8.x4.trans.shared.b16 {%0,%1,%2,%3}, [%4];"
                 : "=r"(r[0]), "=r"(r[1]), "=r"(r[2]), "=r"(r[3]) : "r"(a));
}
__device__ __forceinline__ void hmma(float* c, const uint32_t* a, const uint32_t* b) {
    asm volatile(
        "mma.sync.aligned.m16n8k16.row.col.f32.f16.f16.f32 "
        "{%0,%1,%2,%3}, {%4,%5,%6,%7}, {%8,%9}, {%0,%1,%2,%3};"
        : "+f"(c[0]), "+f"(c[1]), "+f"(c[2]), "+f"(c[3])
        : "r"(a[0]), "r"(a[1]), "r"(a[2]), "r"(a[3]), "r"(b[0]), "r"(b[1]));
}
__device__ __forceinline__ uint32_t packh2(float x, float y) {
    __half2 h = __floats2half2_rn(x, y);
    return *(uint32_t*)&h;
}
__device__ __forceinline__ float gelu_f(float v) {
    // tanh-gelu in exp2 domain: 2*log2(e)*0.7978845608 = 2.3019360227
    float u2 = 2.3019360227f * (v + 0.044715f * v * v * v);
    float t = 1.f - 2.f / (exp2f(u2) + 1.f);
    return 0.5f * v * (1.f + t);
}

// ---------------- K0: convert weights to fp16 ----------------
__global__ __launch_bounds__(256) void k_half(const float* __restrict__ src, int which) {
    __half* dst = which == 0 ? g_w1h : which == 1 ? g_w2h : which == 2 ? g_lu1h :
                  which == 3 ? g_lu2h : which == 4 ? g_ld1h : g_ld2h;
    size_t i = ((size_t)blockIdx.x * 256 + threadIdx.x) * 8;
    float4 v0 = *(const float4*)(src + i);
    float4 v1 = *(const float4*)(src + i + 4);
    __half2 h[4];
    h[0] = __floats2half2_rn(v0.x, v0.y);
    h[1] = __floats2half2_rn(v0.z, v0.w);
    h[2] = __floats2half2_rn(v1.x, v1.y);
    h[3] = __floats2half2_rn(v1.z, v1.w);
    *(uint4*)(dst + i) = *(uint4*)h;
}

// ---------------- K0b: silu(vec) precompute ----------------
__global__ __launch_bounds__(256) void k_silu(const float* __restrict__ vec) {
    int i = blockIdx.x * 256 + threadIdx.x;
    float s = vec[i];
    g_silu[i] = s / (1.f + __expf(-s));
}

// ---------------- K1: mod = silu(vec) @ mod_w^T + mod_b (float4) ----------------
__global__ __launch_bounds__(256) void k_mod(const float* __restrict__ mod_w,
                                             const float* __restrict__ mod_b) {
    int j = blockIdx.x * 8 + (threadIdx.x >> 5);
    int lane = threadIdx.x & 31;
    if (j >= D3H) return;
    const float* wr = mod_w + (size_t)j * HIDC;
    float acc = 0.f;
    #pragma unroll 4
    for (int k = lane * 4; k < HIDC; k += 128) {
        float4 sv = *(const float4*)(g_silu + k);
        float4 wv = *(const float4*)(wr + k);
        acc += sv.x * wv.x + sv.y * wv.y + sv.z * wv.z + sv.w * wv.w;
    }
    #pragma unroll
    for (int o = 16; o; o >>= 1) acc += __shfl_xor_sync(0xffffffffu, acc, o);
    if (lane == 0) g_mod[j] = acc + mod_b[j];
}

// ---------------- K2: LayerNorm + modulation -> g_xmodh (fp16, float4) ----------------
__global__ __launch_bounds__(256) void k_ln(const float* __restrict__ x) {
    __shared__ float rs[8], rs2[8];
    int m = blockIdx.x;
    const float* row = x + (size_t)m * HIDC;
    float4 v[3];
    float s = 0.f, s2 = 0.f;
    #pragma unroll
    for (int i = 0; i < 3; i++) {
        v[i] = *(const float4*)(row + threadIdx.x * 4 + i * 1024);
        s  += v[i].x + v[i].y + v[i].z + v[i].w;
        s2 += v[i].x * v[i].x + v[i].y * v[i].y + v[i].z * v[i].z + v[i].w * v[i].w;
    }
    int lane = threadIdx.x & 31, w = threadIdx.x >> 5;
    #pragma unroll
    for (int o = 16; o; o >>= 1) {
        s  += __shfl_xor_sync(0xffffffffu, s, o);
        s2 += __shfl_xor_sync(0xffffffffu, s2, o);
    }
    if (!lane) { rs[w] = s; rs2[w] = s2; }
    __syncthreads();
    float S = 0.f, S2 = 0.f;
    #pragma unroll
    for (int i = 0; i < 8; i++) { S += rs[i]; S2 += rs2[i]; }
    float mu = S * (1.f / HIDC);
    float var = S2 * (1.f / HIDC) - mu * mu;
    float rstd = rsqrtf(var + 1e-6f);
    __half* orow = g_xmodh + (size_t)m * HIDC;
    #pragma unroll
    for (int i = 0; i < 3; i++) {
        int c = threadIdx.x * 4 + i * 1024;
        float4 sc = *(const float4*)(&g_mod[HIDC + c]);
        float4 sh = *(const float4*)(&g_mod[c]);
        float o0 = (v[i].x - mu) * rstd * (1.f + sc.x) + sh.x;
        float o1 = (v[i].y - mu) * rstd * (1.f + sc.y) + sh.y;
        float o2 = (v[i].z - mu) * rstd * (1.f + sc.z) + sh.z;
        float o3 = (v[i].w - mu) * rstd * (1.f + sc.w) + sh.w;
        __half2 h01 = __floats2half2_rn(o0, o1);
        __half2 h23 = __floats2half2_rn(o2, o3);
        uint2 u = make_uint2(*(uint32_t*)&h01, *(uint32_t*)&h23);
        *(uint2*)(orow + c) = u;
    }
}

// ---------------- K3: low-rank t = A @ ld^T via tensor cores, k-split ----------------
constexpr int LRP = 72;   // smem pitch (halves)

__global__ __launch_bounds__(256) void k_lr(int K, int sel) {
    __shared__ __half smlr[128 * LRP + 32 * LRP];
    uint32_t sb = smem_u32(smlr);
    const __half* A = sel ? g_yh : g_xmodh;
    const __half* L = sel ? g_ld2h : g_ld1h;
    int m0 = blockIdx.x * 128;
    int kl = K / KSPL;
    int k0 = blockIdx.y * kl;
    int tid = threadIdx.x, lane = tid & 31, wid = tid >> 5;
    uint32_t sA = sb, sL = sb + (uint32_t)(128 * LRP) * 2;

    float acc[4][4];
    #pragma unroll
    for (int i = 0; i < 4; i++)
        #pragma unroll
        for (int j = 0; j < 4; j++) acc[i][j] = 0.f;

    for (int kc = 0; kc < kl; kc += 64) {
        #pragma unroll
        for (int j = 0; j < 4; j++) {
            int c = tid + j * 256;
            int r = c >> 3, ch = c & 7;
            cp16s(sA + (uint32_t)(r * LRP + ch * 8) * 2,
                  A + (size_t)(m0 + r) * K + k0 + kc + ch * 8);
        }
        {
            int r = tid >> 3, ch = tid & 7;
            cp16s(sL + (uint32_t)(r * LRP + ch * 8) * 2,
                  L + (size_t)r * K + k0 + kc + ch * 8);
        }
        CP_COMMIT(); CP_WAIT(0);
        __syncthreads();
        #pragma unroll
        for (int ks = 0; ks < 4; ks++) {
            uint32_t af[4];
            int r = wid * 16 + (lane & 15);
            int kc16 = ks * 16 + (lane >> 4) * 8;
            ldsm4(af, sA + (uint32_t)(r * LRP + kc16) * 2);
            uint32_t bf[2][4];
            #pragma unroll
            for (int fn = 0; fn < 2; fn++) {
                int nr = fn * 16 + (lane & 7) + ((lane >> 4) & 1) * 8;
                int kcb = ks * 16 + ((lane >> 3) & 1) * 8;
                ldsm4(bf[fn], sL + (uint32_t)(nr * LRP + kcb) * 2);
            }
            hmma(acc[0], af, &bf[0][0]);
            hmma(acc[1], af, &bf[0][2]);
            hmma(acc[2], af, &bf[1][0]);
            hmma(acc[3], af, &bf[1][2]);
        }
        __syncthreads();
    }

    int g = lane >> 2, tg = lane & 3;
    float* tp = g_tp + (size_t)blockIdx.y * LL * RK;
    int r0 = m0 + wid * 16 + g;
    #pragma unroll
    for (int j = 0; j < 4; j++) {
        tp[(size_t)r0 * RK + j * 8 + 2 * tg]           = acc[j][0];
        tp[(size_t)r0 * RK + j * 8 + 2 * tg + 1]       = acc[j][1];
        tp[(size_t)(r0 + 8) * RK + j * 8 + 2 * tg]     = acc[j][2];
        tp[(size_t)(r0 + 8) * RK + j * 8 + 2 * tg + 1] = acc[j][3];
    }
}

__global__ __launch_bounds__(256) void k_lrsum(int sel) {
    __half* t = sel ? g_t2h : g_t1h;
    int i = blockIdx.x * 256 + threadIdx.x;
    float s = 0.f;
    #pragma unroll
    for (int p = 0; p < KSPL; p++) s += g_tp[(size_t)p * LL * RK + i];
    t[i] = __float2half_rn(s);
}

// ---------------- fp16 mma GEMM: 128x128 tile, k-tile 64, 3 stages, 1 sync/tile ----------------
constexpr int HST = 72;                 // halves per smem row (64 data + 8 pad)
constexpr int TILE_H = 128 * HST;       // 9216 halves
constexpr int STAGE_H = 2 * TILE_H;     // 18432
constexpr int STG = 3;
constexpr int GEMM_SMEM = STG * STAGE_H * 2;  // 110592 B

// EPI==1: A=g_xmodh, fused epilogue -> fp16 q/k/v/gelu(mlp)
// EPI==2: A=g_yh, out = x + gate*(acc+bias) fp32
template <int EPI, int GRP>
__global__ __launch_bounds__(256, 2) void k_gemm(const float* __restrict__ bias,
                                                 float* __restrict__ Cout,
                                                 int K, int N, int ldc,
                                                 const float* __restrict__ xres) {
    extern __shared__ __half smh[];
    uint32_t sb = smem_u32(smh);
    const __half* A  = (EPI == 1) ? g_xmodh : g_yh;
    const __half* TL = (EPI == 1) ? g_t1h : g_t2h;
    const __half* W  = (EPI == 1) ? g_w1h : g_w2h;
    const __half* LU = (EPI == 1) ? g_lu1h : g_lu2h;

    const int NNB = N / 128;
    int bid = blockIdx.x;
    int group = bid / (GRP * NNB);
    int within = bid - group * (GRP * NNB);
    int mb = group * GRP + (within % GRP);
    int nb = within / GRP;
    int m0 = mb << 7, n0 = nb << 7;

    int tid = threadIdx.x, lane = tid & 31, wid = tid >> 5;
    int wm = wid >> 1, wn = wid & 1;               // 4x2 warp grid, warptile 32x64

    const int KTm = K / 64;
    const int KT = KTm + 1;                        // + low-rank tile (zero padded to 64)

    float acc[2][8][4];
    #pragma unroll
    for (int i = 0; i < 2; i++)
        #pragma unroll
        for (int j = 0; j < 8; j++)
            #pragma unroll
            for (int q = 0; q < 4; q++) acc[i][j][q] = 0.f;

    auto issue = [&](int kt) {
        int s = kt % STG;
        uint32_t base = sb + (uint32_t)s * STAGE_H * 2;
        bool mn = kt < KTm;
        #pragma unroll
        for (int j = 0; j < 8; j++) {
            int c = tid + j * 256;                 // 0..2047
            int mat = c >> 10;                     // 0: A, 1: B
            int idx = c & 1023;
            int r = idx >> 3, ch = idx & 7;        // row 0..127, 16B chunk 0..7
            uint32_t dst = base + (uint32_t)(mat * TILE_H + r * HST + ch * 8) * 2;
            const __half* src;
            if (mn) {
                src = mat ? W + (size_t)(n0 + r) * K + kt * 64 + ch * 8
                          : A + (size_t)(m0 + r) * K + kt * 64 + ch * 8;
            } else {
                if (ch < 4)
                    src = mat ? LU + (size_t)(n0 + r) * RK + ch * 8
                              : TL + (size_t)(m0 + r) * RK + ch * 8;
                else
                    src = g_zeroh;
            }
            cp16s(dst, src);
        }
    };

    issue(0); CP_COMMIT();
    issue(1); CP_COMMIT();

    for (int kt = 0; kt < KT; kt++) {
        CP_WAIT(1);
        __syncthreads();
        if (kt + 2 < KT) issue(kt + 2);
        CP_COMMIT();
        uint32_t sA = sb + (uint32_t)(kt % STG) * STAGE_H * 2;
        uint32_t sB = sA + TILE_H * 2;
        #pragma unroll
        for (int ks = 0; ks < 4; ks++) {
            uint32_t af[2][4];
            #pragma unroll
            for (int fm = 0; fm < 2; fm++) {
                int r = wm * 32 + fm * 16 + (lane & 15);
                int kc = ks * 16 + (lane >> 4) * 8;
                ldsm4(af[fm], sA + (uint32_t)(r * HST + kc) * 2);
            }
            uint32_t bf[4][4];
            #pragma unroll
            for (int fp = 0; fp < 4; fp++) {
                int nr = wn * 64 + fp * 16 + (lane & 7) + ((lane >> 4) & 1) * 8;
                int kc = ks * 16 + ((lane >> 3) & 1) * 8;
                ldsm4(bf[fp], sB + (uint32_t)(nr * HST + kc) * 2);
            }
            #pragma unroll
            for (int fm = 0; fm < 2; fm++)
                #pragma unroll
                for (int fn = 0; fn < 8; fn++)
                    hmma(acc[fm][fn], af[fm], &bf[fn >> 1][(fn & 1) * 2]);
        }
    }

    int g = lane >> 2, tg = lane & 3;
    if (EPI == 1) {
        __half* dst;
        size_t stride;
        int cbias;
        bool is_mlp = false;
        if (n0 < HIDC)            { dst = g_qh; stride = HIDC; cbias = 0; }
        else if (n0 < 2 * HIDC)   { dst = g_kh; stride = HIDC; cbias = HIDC; }
        else if (n0 < D3H)        { dst = g_vh; stride = HIDC; cbias = 2 * HIDC; }
        else { dst = g_yh; stride = NCAT; cbias = D3H - HIDC; is_mlp = true; }
        #pragma unroll
        for (int fm = 0; fm < 2; fm++) {
            int r0 = m0 + wm * 32 + fm * 16 + g;
            int r1 = r0 + 8;
            #pragma unroll
            for (int fn = 0; fn < 8; fn++) {
                int cc = n0 + wn * 64 + fn * 8 + 2 * tg;
                float v0 = acc[fm][fn][0] + bias[cc];
                float v1 = acc[fm][fn][1] + bias[cc + 1];
                float v2 = acc[fm][fn][2] + bias[cc];
                float v3 = acc[fm][fn][3] + bias[cc + 1];
                if (is_mlp) {
                    v0 = gelu_f(v0); v1 = gelu_f(v1);
                    v2 = gelu_f(v2); v3 = gelu_f(v3);
                }
                int col = cc - cbias;
                *(__half2*)(dst + (size_t)r0 * stride + col) = __floats2half2_rn(v0, v1);
                *(__half2*)(dst + (size_t)r1 * stride + col) = __floats2half2_rn(v2, v3);
            }
        }
    } else {
        #pragma unroll
        for (int fm = 0; fm < 2; fm++) {
            int r0 = m0 + wm * 32 + fm * 16 + g;
            int r1 = r0 + 8;
            #pragma unroll
            for (int fn = 0; fn < 8; fn++) {
                int cc = n0 + wn * 64 + fn * 8 + 2 * tg;
                float v0 = acc[fm][fn][0] + bias[cc];
                float v1 = acc[fm][fn][1] + bias[cc + 1];
                float v2 = acc[fm][fn][2] + bias[cc];
                float v3 = acc[fm][fn][3] + bias[cc + 1];
                float gt0 = g_mod[2 * HIDC + cc], gt1 = g_mod[2 * HIDC + cc + 1];
                v0 = xres[(size_t)r0 * ldc + cc]     + gt0 * v0;
                v1 = xres[(size_t)r0 * ldc + cc + 1] + gt1 * v1;
                v2 = xres[(size_t)r1 * ldc + cc]     + gt0 * v2;
                v3 = xres[(size_t)r1 * ldc + cc + 1] + gt1 * v3;
                *(float2*)(Cout + (size_t)r0 * ldc + cc) = make_float2(v0, v1);
                *(float2*)(Cout + (size_t)r1 * ldc + cc) = make_float2(v2, v3);
            }
        }
    }
}

// ---------------- K5: RMSNorm(q,k) + RoPE, warp-per-row, vectorized ----------------
__global__ __launch_bounds__(256) void k_qknorm(const float* __restrict__ pe,
                                                const float* __restrict__ rqw,
                                                const float* __restrict__ rkw) {
    int lane = threadIdx.x & 31, wid = threadIdx.x >> 5;
    int l = blockIdx.x;
    int h = blockIdx.y * 8 + wid;
    size_t base = (size_t)l * HIDC + (size_t)h * 128 + lane * 4;

    // load 4 halves of q and k
    uint2 qu = *(const uint2*)(g_qh + base);
    uint2 ku = *(const uint2*)(g_kh + base);
    float2 q01 = __half22float2(*(__half2*)&qu.x);
    float2 q23 = __half22float2(*(__half2*)&qu.y);
    float2 k01 = __half22float2(*(__half2*)&ku.x);
    float2 k23 = __half22float2(*(__half2*)&ku.y);

    float q2 = q01.x * q01.x + q01.y * q01.y + q23.x * q23.x + q23.y * q23.y;
    float k2 = k01.x * k01.x + k01.y * k01.y + k23.x * k23.x + k23.y * k23.y;
    #pragma unroll
    for (int o = 16; o; o >>= 1) {
        q2 += __shfl_xor_sync(0xffffffffu, q2, o);
        k2 += __shfl_xor_sync(0xffffffffu, k2, o);
    }
    float qr = rsqrtf(q2 * (1.f / HDC) + 1e-6f);
    float kr = rsqrtf(k2 * (1.f / HDC) + 1e-6f);

    float4 w4q = *(const float4*)(rqw + lane * 4);
    float4 w4k = *(const float4*)(rkw + lane * 4);
    float qn0 = q01.x * qr * w4q.x, qn1 = q01.y * qr * w4q.y;
    float qn2 = q23.x * qr * w4q.z, qn3 = q23.y * qr * w4q.w;
    float kn0 = k01.x * kr * w4k.x, kn1 = k01.y * kr * w4k.y;
    float kn2 = k23.x * kr * w4k.z, kn3 = k23.y * kr * w4k.w;

    // RoPE: pairs p0 = 2*lane, p1 = 2*lane+1; rot float4 = [r00,r01,r10,r11]
    const float* pl = pe + (size_t)l * 256;   // 64 pairs * 4 floats
    float4 r0 = *(const float4*)(pl + (2 * lane) * 4);
    float4 r1 = *(const float4*)(pl + (2 * lane + 1) * 4);

    float qo0 = r0.x * qn0 + r0.y * qn1;
    float qo1 = r0.z * qn0 + r0.w * qn1;
    float qo2 = r1.x * qn2 + r1.y * qn3;
    float qo3 = r1.z * qn2 + r1.w * qn3;
    float ko0 = r0.x * kn0 + r0.y * kn1;
    float ko1 = r0.z * kn0 + r0.w * kn1;
    float ko2 = r1.x * kn2 + r1.y * kn3;
    float ko3 = r1.z * kn2 + r1.w * kn3;

    __half2 qh01 = __floats2half2_rn(qo0, qo1);
    __half2 qh23 = __floats2half2_rn(qo2, qo3);
    __half2 kh01 = __floats2half2_rn(ko0, ko1);
    __half2 kh23 = __floats2half2_rn(ko2, ko3);
    *(uint2*)(g_qh + base) = make_uint2(*(uint32_t*)&qh01, *(uint32_t*)&qh23);
    *(uint2*)(g_kh + base) = make_uint2(*(uint32_t*)&kh01, *(uint32_t*)&kh23);
}

// ---------------- K6: fp16 flash attention, 256q x 64k, 512 thr, shared K/V stream ----------------
constexpr int AST = 136;                        // halves per smem row
constexpr int OQ = 0;
constexpr int OS = 256 * AST;                   // stages base (after 256-row Q)
constexpr int STAGE_ATT = 128 * AST;            // per stage: K 64 rows + V 64 rows
constexpr int ATT_H = OS + 2 * STAGE_ATT;       // 69632 halves
constexpr int ATT_SMEM = ATT_H * 2;             // 139264 B

__global__ __launch_bounds__(512, 1) void k_attn() {
    extern __shared__ __half smh[];
    uint32_t sb = smem_u32(smh);

    int tid = threadIdx.x, lane = tid & 31, wid = tid >> 5;   // wid 0..15
    int g = lane >> 2, tg = lane & 3;
    int q0 = blockIdx.x * 256, h = blockIdx.y;
    size_t hb = (size_t)h * 128;
    const float sl2e = 0.08838834764831845f * 1.4426950408889634f;  // scale * log2(e)
    const int NKB = LL / 64;

    // load Q tile (256 rows, plain loads, once)
    for (int i = tid; i < 256 * 16; i += 512) {
        int r = i >> 4, c = (i & 15) * 8;
        *(uint4*)(smh + OQ + r * AST + c) =
            *(const uint4*)(g_qh + (size_t)(q0 + r) * HIDC + hb + c);
    }

    auto issueKV = [&](int kb) {
        uint32_t base = sb + (uint32_t)(OS + (kb & 1) * STAGE_ATT) * 2;
        int k0 = kb * 64;
        #pragma unroll
        for (int j = 0; j < 4; j++) {
            int c = tid + j * 512;                 // 0..2047
            int mat = c >> 10;                     // 0: K, 1: V
            int idx = c & 1023;
            int r = idx >> 4, ch = idx & 15;
            const __half* src = (mat ? g_vh : g_kh) + (size_t)(k0 + r) * HIDC + hb + ch * 8;
            uint32_t dst = base + (uint32_t)((mat * 64 + r) * AST + ch * 8) * 2;
            cp16s(dst, src);
        }
    };

    issueKV(0); CP_COMMIT();
    __syncthreads();

    float m0r = -1e30f, m1r = -1e30f, l0r = 0.f, l1r = 0.f;
    float oacc[16][4];
    #pragma unroll
    for (int i = 0; i < 16; i++)
        #pragma unroll
        for (int j = 0; j < 4; j++) oacc[i][j] = 0.f;

    for (int kb = 0; kb < NKB; kb++) {
        CP_WAIT(0);
        __syncthreads();
        if (kb + 1 < NKB) { issueKV(kb + 1); CP_COMMIT(); }
        uint32_t sK = sb + (uint32_t)(OS + (kb & 1) * STAGE_ATT) * 2;
        uint32_t sV = sK + (uint32_t)(64 * AST) * 2;

        // S = Q K^T  (Q frags from smem each ks)
        float sacc[8][4];
        #pragma unroll
        for (int i = 0; i < 8; i++)
            #pragma unroll
            for (int j = 0; j < 4; j++) sacc[i][j] = 0.f;
        #pragma unroll
        for (int ks = 0; ks < 8; ks++) {
            uint32_t qf[4];
            {
                int r = wid * 16 + (lane & 15);
                int kc = ks * 16 + (lane >> 4) * 8;
                ldsm4(qf, sb + (uint32_t)(OQ + r * AST + kc) * 2);
            }
            #pragma unroll
            for (int fp = 0; fp < 4; fp++) {
                uint32_t bf[4];
                int nr = fp * 16 + (lane & 7) + ((lane >> 4) & 1) * 8;
                int kc = ks * 16 + ((lane >> 3) & 1) * 8;
                ldsm4(bf, sK + (uint32_t)(nr * AST + kc) * 2);
                hmma(sacc[2 * fp], qf, &bf[0]);
                hmma(sacc[2 * fp + 1], qf, &bf[2]);
            }
        }

        // online softmax (base-2 domain)
        float mx0 = -1e30f, mx1 = -1e30f;
        #pragma unroll
        for (int fn = 0; fn < 8; fn++) {
            sacc[fn][0] *= sl2e; sacc[fn][1] *= sl2e;
            sacc[fn][2] *= sl2e; sacc[fn][3] *= sl2e;
            mx0 = fmaxf(mx0, fmaxf(sacc[fn][0], sacc[fn][1]));
            mx1 = fmaxf(mx1, fmaxf(sacc[fn][2], sacc[fn][3]));
        }
        mx0 = fmaxf(mx0, __shfl_xor_sync(0xffffffffu, mx0, 1));
        mx0 = fmaxf(mx0, __shfl_xor_sync(0xffffffffu, mx0, 2));
        mx1 = fmaxf(mx1, __shfl_xor_sync(0xffffffffu, mx1, 1));
        mx1 = fmaxf(mx1, __shfl_xor_sync(0xffffffffu, mx1, 2));
        float mn0 = fmaxf(m0r, mx0), mn1 = fmaxf(m1r, mx1);
        float cr0 = exp2f(m0r - mn0), cr1 = exp2f(m1r - mn1);
        float s0 = 0.f, s1 = 0.f;
        #pragma unroll
        for (int fn = 0; fn < 8; fn++) {
            sacc[fn][0] = exp2f(sacc[fn][0] - mn0);
            sacc[fn][1] = exp2f(sacc[fn][1] - mn0);
            sacc[fn][2] = exp2f(sacc[fn][2] - mn1);
            sacc[fn][3] = exp2f(sacc[fn][3] - mn1);
            s0 += sacc[fn][0] + sacc[fn][1];
            s1 += sacc[fn][2] + sacc[fn][3];
        }
        s0 += __shfl_xor_sync(0xffffffffu, s0, 1);
        s0 += __shfl_xor_sync(0xffffffffu, s0, 2);
        s1 += __shfl_xor_sync(0xffffffffu, s1, 1);
        s1 += __shfl_xor_sync(0xffffffffu, s1, 2);
        l0r = l0r * cr0 + s0;
        l1r = l1r * cr1 + s1;
        m0r = mn0; m1r = mn1;
        #pragma unroll
        for (int fn = 0; fn < 16; fn++) {
            oacc[fn][0] *= cr0; oacc[fn][1] *= cr0;
            oacc[fn][2] *= cr1; oacc[fn][3] *= cr1;
        }

        // O += P V
        #pragma unroll
        for (int ks = 0; ks < 4; ks++) {
            uint32_t pa[4];
            pa[0] = packh2(sacc[2 * ks][0],     sacc[2 * ks][1]);
            pa[1] = packh2(sacc[2 * ks][2],     sacc[2 * ks][3]);
            pa[2] = packh2(sacc[2 * ks + 1][0], sacc[2 * ks + 1][1]);
            pa[3] = packh2(sacc[2 * ks + 1][2], sacc[2 * ks + 1][3]);
            #pragma unroll
            for (int fp = 0; fp < 8; fp++) {
                uint32_t bf[4];
                int kr = ks * 16 + (lane & 7) + ((lane >> 3) & 1) * 8;
                int dc = fp * 16 + (lane >> 4) * 8;
                ldsm4t(bf, sV + (uint32_t)(kr * AST + dc) * 2);
                hmma(oacc[2 * fp], pa, &bf[0]);
                hmma(oacc[2 * fp + 1], pa, &bf[2]);
            }
        }
    }

    float inv0 = 1.f / l0r, inv1 = 1.f / l1r;
    int r0 = q0 + wid * 16 + g;
    #pragma unroll
    for (int fn = 0; fn < 16; fn++) {
        int c = (int)hb + fn * 8 + 2 * tg;
        *(__half2*)(g_yh + (size_t)r0 * NCAT + c) =
            __floats2half2_rn(oacc[fn][0] * inv0, oacc[fn][1] * inv0);
        *(__half2*)(g_yh + (size_t)(r0 + 8) * NCAT + c) =
            __floats2half2_rn(oacc[fn][2] * inv1, oacc[fn][3] * inv1);
    }
}

// ---------------- launch ----------------
extern "C" void kernel_launch(void* const* d_in, const int* in_sizes, int n_in,
                              void* d_out, int out_size) {
    const float* x     = (const float*)d_in[0];
    const float* vec   = (const float*)d_in[1];
    const float* pe    = (const float*)d_in[2];
    const float* mod_w = (const float*)d_in[3];
    const float* mod_b = (const float*)d_in[4];
    const float* w1    = (const float*)d_in[5];
    const float* b1    = (const float*)d_in[6];
    const float* ld1   = (const float*)d_in[7];
    const float* lu1   = (const float*)d_in[8];
    const float* w2    = (const float*)d_in[9];
    const float* b2    = (const float*)d_in[10];
    const float* ld2   = (const float*)d_in[11];
    const float* lu2   = (const float*)d_in[12];
    const float* rqw   = (const float*)d_in[13];
    const float* rkw   = (const float*)d_in[14];
    float* out = (float*)d_out;

    cudaFuncSetAttribute(k_attn, cudaFuncAttributeMaxDynamicSharedMemorySize, ATT_SMEM);
    cudaFuncSetAttribute((const void*)k_gemm<1, 36>, cudaFuncAttributeMaxDynamicSharedMemorySize, GEMM_SMEM);
    cudaFuncSetAttribute((const void*)k_gemm<2, 18>, cudaFuncAttributeMaxDynamicSharedMemorySize, GEMM_SMEM);

    k_silu<<<HIDC / 256, 256>>>(vec);
    k_mod<<<D3H / 8, 256>>>(mod_w, mod_b);
    k_half<<<RK * HIDC / 2048, 256>>>(ld1, 4);
    k_half<<<(int)((size_t)NQKV * HIDC / 2048), 256>>>(w1, 0);
    k_ln<<<LL, 256>>>(x);
    {
        dim3 glr(LL / 128, KSPL);
        k_lr<<<glr, 256>>>(HIDC, 0);
        k_lrsum<<<LL * RK / 256, 256>>>(0);
    }
    k_half<<<NQKV * RK / 2048, 256>>>(lu1, 2);
    {
        int nblocks = (LL / 128) * (NQKV / 128);   // 36 * 168
        k_gemm<1, 36><<<nblocks, 256, GEMM_SMEM>>>(b1, nullptr, HIDC, NQKV, NQKV, nullptr);
    }
    {
        dim3 gq(LL, NHC / 8);   // (4608, 3), 8 heads per block
        k_qknorm<<<gq, 256>>>(pe, rqw, rkw);
    }
    {
        dim3 ga(LL / 256, NHC);   // (18, 24)
        k_attn<<<ga, 512, ATT_SMEM>>>();
    }
    k_half<<<RK * NCAT / 2048, 256>>>(ld2, 5);
    {
        dim3 glr(LL / 128, KSPL);
        k_lr<<<glr, 256>>>(NCAT, 1);
        k_lrsum<<<LL * RK / 256, 256>>>(1);
    }
    k_half<<<(int)((size_t)HIDC * NCAT / 2048), 256>>>(w2, 1);
    k_half<<<HIDC * RK / 2048, 256>>>(lu2, 3);
    {
        int nblocks = (LL / 128) * (HIDC / 128);   // 36 * 24
        k_gemm<2, 18><<<nblocks, 256, GEMM_SMEM>>>(b2, out, NCAT, HIDC, HIDC, x);
    }
}